// round 13
// baseline (speedup 1.0000x reference)
#include <cuda_runtime.h>
#include <cuda_bf16.h>
#include <cstdint>

// ---------------- problem constants ----------------
#define N_ROWS   65536
#define K_CODES  1024
#define D_DIM    64
#define M_TILE   128                    // rows per CTA
#define THREADS  256
#define NUM_BLOCKS (N_ROWS / M_TILE)    // 512
#define N_MB     (N_ROWS / 16)          // 4096 A row-blocks
#define N_NB     (K_CODES / 8)          // 128 B code-blocks
#define NBL_T    8                      // nblocks per staged B tile
#define N_TILES  (N_NB / NBL_T)         // 16
#define CAP      48
#define MARGIN   0.0625f

// Output layout (floats): [quantized 4194304][loss 1][indices 65536]
#define OUT_LOSS (N_ROWS * D_DIM)
#define OUT_IDX  (OUT_LOSS + 1)

// ---------------- device globals ----------------
__device__ uint32_t g_Ah[N_MB * 4 * 32 * 4];   // 8 MB
__device__ uint32_t g_Am[N_MB * 4 * 32 * 4];   // 8 MB
__device__ uint32_t g_Bh[N_NB * 4 * 32 * 2];   // 128 KB
__device__ uint32_t g_Bm[N_NB * 4 * 32 * 2];   // 128 KB
__device__ float g_normE[K_CODES];
__device__ float g_partials[NUM_BLOCKS];

// ---------------- smem layout (bytes) ----------------
#define SM_B     0        // 16384: [plane(2)][nbl(8)][kb(4)][lane(32)] uint2
#define SM_AMID  16384    // 16384: [warp(8)][kb(4)][lane(32)] uint4
#define SM_NORM  32768    // 4096
#define SM_CANDV 36864    // 24576: 128 * CAP floats
#define SM_CANDI 61440    // 12288: 128 * CAP u16
#define SM_CNT   73728    // 512
#define SM_TOTAL 74240    // 72.5 KB -> 3 CTAs/SM

// ---------------- helpers ----------------
__device__ __forceinline__ uint32_t pack_bf16(float lo, float hi) {
    __nv_bfloat16 a = __float2bfloat16(lo);
    __nv_bfloat16 b = __float2bfloat16(hi);
    uint16_t ua = *(uint16_t*)&a, ub = *(uint16_t*)&b;
    return (uint32_t)ua | ((uint32_t)ub << 16);
}
__device__ __forceinline__ float bf16val(float v) {
    __nv_bfloat16 b = __float2bfloat16(v);
    return __bfloat162float(b);
}
__device__ __forceinline__ void mma_bf16(float* c, const uint32_t* a,
                                         uint32_t b0, uint32_t b1) {
    asm volatile(
        "mma.sync.aligned.m16n8k16.row.col.f32.bf16.bf16.f32 "
        "{%0,%1,%2,%3}, {%4,%5,%6,%7}, {%8,%9}, {%0,%1,%2,%3};"
        : "+f"(c[0]), "+f"(c[1]), "+f"(c[2]), "+f"(c[3])
        : "r"(a[0]), "r"(a[1]), "r"(a[2]), "r"(a[3]), "r"(b0), "r"(b1));
}
__device__ __forceinline__ float exact_dist(const float4* xr4, const float* E,
                                            int c, float ne) {
    const float4* er4 = (const float4*)(E + (size_t)c * D_DIM);
    float dot = 0.f;
#pragma unroll
    for (int i = 0; i < D_DIM / 4; ++i) {
        float4 x = xr4[i], e = er4[i];
        dot = fmaf(x.x, e.x, dot); dot = fmaf(x.y, e.y, dot);
        dot = fmaf(x.z, e.z, dot); dot = fmaf(x.w, e.w, dot);
    }
    return fmaf(-2.f, dot, ne);
}

// ---------------------------------------------------------------------------
// Prep A: split (-2*X) into (hi, mid) bf16 planes, mma-fragment order
// ---------------------------------------------------------------------------
__global__ void vq_prepA(const float* __restrict__ X) {
    int tid = blockIdx.x * blockDim.x + threadIdx.x;
    if (tid >= N_MB * 4 * 32 * 4) return;
    int reg = tid & 3, lane = (tid >> 2) & 31, kb = (tid >> 7) & 3, mb = tid >> 9;
    int g = lane >> 2, tg = lane & 3;
    int row = mb * 16 + g + ((reg & 1) << 3);
    int col = kb * 16 + tg * 2 + ((reg & 2) << 2);
    const float* xp = X + (size_t)row * D_DIM + col;
    float v0 = -2.0f * xp[0], v1 = -2.0f * xp[1];
    float h0 = bf16val(v0), h1 = bf16val(v1);
    g_Ah[tid] = pack_bf16(v0, v1);
    g_Am[tid] = pack_bf16(v0 - h0, v1 - h1);
}

// ---------------------------------------------------------------------------
// Prep B: split E into (hi, mid) bf16 planes, mma-fragment order
// ---------------------------------------------------------------------------
__global__ void vq_prepB(const float* __restrict__ E) {
    int tid = blockIdx.x * blockDim.x + threadIdx.x;
    if (tid >= N_NB * 4 * 32 * 2) return;
    int reg = tid & 1, lane = (tid >> 1) & 31, kb = (tid >> 6) & 3, nb = tid >> 8;
    int g = lane >> 2, tg = lane & 3;
    int code = nb * 8 + g;
    int k = kb * 16 + tg * 2 + reg * 8;
    const float* ep = E + (size_t)code * D_DIM + k;
    float v0 = ep[0], v1 = ep[1];
    float h0 = bf16val(v0), h1 = bf16val(v1);
    g_Bh[tid] = pack_bf16(v0, v1);
    g_Bm[tid] = pack_bf16(v0 - h0, v1 - h1);
}

// ---------------------------------------------------------------------------
// Codebook norms
// ---------------------------------------------------------------------------
__global__ void vq_norm_kernel(const float* __restrict__ E) {
    int k = blockIdx.x * blockDim.x + threadIdx.x;
    if (k < K_CODES) {
        const float4* e = (const float4*)(E + (size_t)k * D_DIM);
        float s = 0.f;
#pragma unroll
        for (int i = 0; i < D_DIM / 4; ++i) {
            float4 v = e[i];
            s += v.x * v.x + v.y * v.y + v.z * v.z + v.w * v.w;
        }
        g_normE[k] = s;
    }
}

// ---------------------------------------------------------------------------
// Main: HMMA split distance GEMM; aM fragments live in SMEM (register diet),
//       small B tiles, 3 CTAs/SM for latency cover; value-pruned exact refine
// ---------------------------------------------------------------------------
__global__ __launch_bounds__(THREADS, 3) void vq_main_kernel(
    const float* __restrict__ X, const float* __restrict__ E,
    float* __restrict__ out)
{
    extern __shared__ char smem[];
    float* snorm = (float*)(smem + SM_NORM);
    float* candV = (float*)(smem + SM_CANDV);
    unsigned short* candI = (unsigned short*)(smem + SM_CANDI);
    int* cnt = (int*)(smem + SM_CNT);

    const int t = threadIdx.x;
    const int w = t >> 5, l = t & 31;
    const int g = l >> 2, tg = l & 3;
    const int rowBase = blockIdx.x * M_TILE;

    if (t < M_TILE) cnt[t] = 0;
    for (int i = t; i < K_CODES; i += THREADS) snorm[i] = g_normE[i];

    // A-hi fragments in registers for this warp's 16 rows
    const int mb = blockIdx.x * 8 + w;
    uint4 aH[4];
#pragma unroll
    for (int kb = 0; kb < 4; ++kb)
        aH[kb] = *(const uint4*)&g_Ah[((mb * 4 + kb) * 32 + l) * 4];

    // stage A-mid fragments for all 8 warps into SMEM (loaded per-iteration)
    {
        uint4* amidDst = (uint4*)(smem + SM_AMID);
#pragma unroll
        for (int i = 0; i < 4; ++i) {
            int idx = t + i * THREADS;        // < 1024
            int w2 = idx >> 7, rem = idx & 127;
            int kb2 = rem >> 5, l2 = rem & 31;
            amidDst[idx] = *(const uint4*)
                &g_Am[(((blockIdx.x * 8 + w2) * 4 + kb2) * 32 + l2) * 4];
        }
    }

    float minv0 = 3.4e38f, minv1 = 3.4e38f;
    const int rL0 = w * 16 + g, rL1 = rL0 + 8;
    const uint4* amid = (const uint4*)(smem + SM_AMID) + w * 128 + l;  // + kb*32

#pragma unroll 1
    for (int tile = 0; tile < N_TILES; ++tile) {
        __syncthreads();
        // stage B tile (8 nblocks, both planes) = 16KB
        {
            const uint4* srcH = (const uint4*)(g_Bh + tile * 2048);
            const uint4* srcM = (const uint4*)(g_Bm + tile * 2048);
            uint4* dst = (uint4*)(smem + SM_B);
#pragma unroll
            for (int i = 0; i < 4; ++i) {
                int idx = t + i * THREADS;     // < 1024
                dst[idx] = (idx < 512) ? srcH[idx] : srcM[idx - 512];
            }
        }
        __syncthreads();

        const uint2* bq = (const uint2*)(smem + SM_B) + l;
#pragma unroll 1
        for (int nbl = 0; nbl < NBL_T; ++nbl) {
            uint2 cbh[4], cbm[4];
#pragma unroll
            for (int kb = 0; kb < 4; ++kb) {
                cbh[kb] = bq[kb * 32];
                cbm[kb] = bq[1024 + kb * 32];
            }
            bq += 128;

            const int c0 = tile * 64 + nbl * 8 + tg * 2;
            const float2 nn = *(const float2*)&snorm[c0];
            float hh[4] = {0.f, 0.f, 0.f, 0.f};
            float hm[4] = {0.f, 0.f, 0.f, 0.f};
            float mh[4] = {nn.x, nn.y, nn.x, nn.y};   // norm folded in
#pragma unroll
            for (int kb = 0; kb < 4; ++kb) {
                uint4 am = amid[kb * 32];
                mma_bf16(hh, (const uint32_t*)&aH[kb], cbh[kb].x, cbh[kb].y);
                mma_bf16(hm, (const uint32_t*)&aH[kb], cbm[kb].x, cbm[kb].y);
                mma_bf16(mh, (const uint32_t*)&am, cbh[kb].x, cbh[kb].y);
            }
            const float d0 = hh[0] + hm[0] + mh[0];
            const float d1 = hh[1] + hm[1] + mh[1];
            const float d2 = hh[2] + hm[2] + mh[2];
            const float d3 = hh[3] + hm[3] + mh[3];
            // rare guard; store approx value + index for later pruning
            if (fminf(d0, d1) < minv0 + MARGIN || fminf(d2, d3) < minv1 + MARGIN) {
                if (d0 < minv0 + MARGIN) {
                    int p = atomicAdd(&cnt[rL0], 1);
                    if (p < CAP) { candV[rL0 * CAP + p] = d0; candI[rL0 * CAP + p] = (unsigned short)c0; }
                }
                minv0 = fminf(minv0, d0);
                if (d1 < minv0 + MARGIN) {
                    int p = atomicAdd(&cnt[rL0], 1);
                    if (p < CAP) { candV[rL0 * CAP + p] = d1; candI[rL0 * CAP + p] = (unsigned short)(c0 + 1); }
                }
                minv0 = fminf(minv0, d1);
                if (d2 < minv1 + MARGIN) {
                    int p = atomicAdd(&cnt[rL1], 1);
                    if (p < CAP) { candV[rL1 * CAP + p] = d2; candI[rL1 * CAP + p] = (unsigned short)c0; }
                }
                minv1 = fminf(minv1, d2);
                if (d3 < minv1 + MARGIN) {
                    int p = atomicAdd(&cnt[rL1], 1);
                    if (p < CAP) { candV[rL1 * CAP + p] = d3; candI[rL1 * CAP + p] = (unsigned short)(c0 + 1); }
                }
                minv1 = fminf(minv1, d3);
            } else {
                minv0 = fminf(minv0, fminf(d0, d1));
                minv1 = fminf(minv1, fminf(d2, d3));
            }
        }
    }
    __syncthreads();

    // ---- value-pruned exact refine + epilogue: one thread per row ----
    float* sLoss = (float*)(smem + SM_B);   // reuse B area
    if (t < M_TILE) {
        const int r = t;
        const float4* xr4 = (const float4*)(X + (size_t)(rowBase + r) * D_DIM);
        float bv = 3.4e38f;
        int bi = K_CODES;
        const int count = cnt[r];
        if (count > CAP) {
            for (int c = 0; c < K_CODES; ++c) {
                float dv = exact_dist(xr4, E, c, g_normE[c]);
                if (dv < bv) { bv = dv; bi = c; }
            }
        } else {
            float mA = 3.4e38f;
            for (int i = 0; i < count; ++i)
                mA = fminf(mA, candV[r * CAP + i]);
            for (int i = 0; i < count; ++i) {
                if (candV[r * CAP + i] > mA + MARGIN) continue;
                int c = candI[r * CAP + i];
                float dv = exact_dist(xr4, E, c, g_normE[c]);
                if (dv < bv || (dv == bv && c < bi)) { bv = dv; bi = c; }
            }
        }
        const float4* erow = (const float4*)(E + (size_t)bi * D_DIM);
        float* qout = out + (size_t)(rowBase + r) * D_DIM;
        float lsum = 0.f;
#pragma unroll
        for (int i = 0; i < D_DIM / 4; ++i) {
            float4 q = erow[i], x = xr4[i];
            float e0 = q.x - x.x, e1 = q.y - x.y, e2 = q.z - x.z, e3 = q.w - x.w;
            lsum += e0 * e0 + e1 * e1 + e2 * e2 + e3 * e3;
            *(float4*)(qout + i * 4) = q;
        }
        out[OUT_IDX + rowBase + r] = (float)bi;
        sLoss[r] = lsum;
    }
    __syncthreads();
    if (t < 64) sLoss[t] += sLoss[t + 64];
    __syncthreads();
    if (t < 32) sLoss[t] += sLoss[t + 32];
    __syncthreads();
    if (t == 0) {
        float s = 0.f;
#pragma unroll
        for (int i = 0; i < 32; ++i) s += sLoss[i];
        g_partials[blockIdx.x] = s;
    }
}

// ---------------------------------------------------------------------------
// Final loss:  loss = 1.25 * mean((q - x)^2), deterministic tree
// ---------------------------------------------------------------------------
__global__ void vq_loss_kernel(float* __restrict__ out) {
    __shared__ float sh[NUM_BLOCKS];
    int t = threadIdx.x;
    sh[t] = g_partials[t];
    __syncthreads();
    for (int s = NUM_BLOCKS / 2; s > 0; s >>= 1) {
        if (t < s) sh[t] += sh[t + s];
        __syncthreads();
    }
    if (t == 0) out[OUT_LOSS] = sh[0] * (1.25f / (float)(N_ROWS * D_DIM));
}

// ---------------------------------------------------------------------------
extern "C" void kernel_launch(void* const* d_in, const int* in_sizes, int n_in,
                              void* d_out, int out_size) {
    const float* X = (const float*)d_in[0];
    const float* E = (const float*)d_in[1];
    float* out = (float*)d_out;

    cudaFuncSetAttribute(vq_main_kernel,
                         cudaFuncAttributeMaxDynamicSharedMemorySize, SM_TOTAL);

    vq_prepA<<<(N_MB * 4 * 32 * 4 + 255) / 256, 256>>>(X);
    vq_prepB<<<(N_NB * 4 * 32 * 2 + 255) / 256, 256>>>(E);
    vq_norm_kernel<<<(K_CODES + 255) / 256, 256>>>(E);
    vq_main_kernel<<<NUM_BLOCKS, THREADS, SM_TOTAL>>>(X, E, out);
    vq_loss_kernel<<<1, NUM_BLOCKS>>>(out);
}

// round 14
// speedup vs baseline: 1.2889x; 1.2889x over previous
#include <cuda_runtime.h>
#include <cuda_bf16.h>
#include <cstdint>

// ---------------- problem constants ----------------
#define N_ROWS   65536
#define K_CODES  1024
#define D_DIM    64
#define M_TILE   128                    // rows per CTA
#define THREADS  256
#define NUM_BLOCKS (N_ROWS / M_TILE)    // 512
#define N_MB     (N_ROWS / 16)          // 4096 A row-blocks
#define N_NB     (K_CODES / 8)          // 128 B code-blocks
#define CAP      80
#define MARGIN   1.0f

// Output layout (floats): [quantized 4194304][loss 1][indices 65536]
#define OUT_LOSS (N_ROWS * D_DIM)
#define OUT_IDX  (OUT_LOSS + 1)

// ---------------- device globals ----------------
// A fragments (hi plane of -2X): [mb][kb][lane][reg] u32, mma m16n8k16 order
__device__ uint32_t g_Ah[N_MB * 4 * 32 * 4];   // 8 MB
// B fragments (hi plane of E): [nb][kb][lane][reg(2)] u32
__device__ uint32_t g_Bh[N_NB * 4 * 32 * 2];   // 128 KB
__device__ float g_normE[K_CODES];
__device__ float g_partials[NUM_BLOCKS];

// ---------------- smem layout (bytes) ----------------
#define SM_B     0        // 32768: [nbl(32)][kb(4)][lane(32)] uint2
#define SM_NORM  32768    // 4096: 1024 floats
#define SM_CANDV 36864    // 40960: 128 * CAP floats
#define SM_CANDI 77824    // 20480: 128 * CAP u16
#define SM_CNT   98304    // 512
#define SM_TOTAL 98816    // 96.5 KB -> 2 CTAs/SM

// ---------------- helpers ----------------
__device__ __forceinline__ uint32_t pack_bf16(float lo, float hi) {
    __nv_bfloat16 a = __float2bfloat16(lo);
    __nv_bfloat16 b = __float2bfloat16(hi);
    uint16_t ua = *(uint16_t*)&a, ub = *(uint16_t*)&b;
    return (uint32_t)ua | ((uint32_t)ub << 16);
}
__device__ __forceinline__ void mma_bf16(float* c, const uint32_t* a,
                                         uint32_t b0, uint32_t b1) {
    asm volatile(
        "mma.sync.aligned.m16n8k16.row.col.f32.bf16.bf16.f32 "
        "{%0,%1,%2,%3}, {%4,%5,%6,%7}, {%8,%9}, {%0,%1,%2,%3};"
        : "+f"(c[0]), "+f"(c[1]), "+f"(c[2]), "+f"(c[3])
        : "r"(a[0]), "r"(a[1]), "r"(a[2]), "r"(a[3]), "r"(b0), "r"(b1));
}
__device__ __forceinline__ float exact_dist(const float4* xr4, const float* E,
                                            int c, float ne) {
    const float4* er4 = (const float4*)(E + (size_t)c * D_DIM);
    float dot = 0.f;
#pragma unroll
    for (int i = 0; i < D_DIM / 4; ++i) {
        float4 x = xr4[i], e = er4[i];
        dot = fmaf(x.x, e.x, dot); dot = fmaf(x.y, e.y, dot);
        dot = fmaf(x.z, e.z, dot); dot = fmaf(x.w, e.w, dot);
    }
    return fmaf(-2.f, dot, ne);
}

// ---------------------------------------------------------------------------
// Prep A: (-2*X) -> bf16 hi plane, mma-fragment order
// ---------------------------------------------------------------------------
__global__ void vq_prepA(const float* __restrict__ X) {
    int tid = blockIdx.x * blockDim.x + threadIdx.x;
    if (tid >= N_MB * 4 * 32 * 4) return;
    int reg = tid & 3, lane = (tid >> 2) & 31, kb = (tid >> 7) & 3, mb = tid >> 9;
    int g = lane >> 2, tg = lane & 3;
    int row = mb * 16 + g + ((reg & 1) << 3);
    int col = kb * 16 + tg * 2 + ((reg & 2) << 2);
    const float* xp = X + (size_t)row * D_DIM + col;
    g_Ah[tid] = pack_bf16(-2.0f * xp[0], -2.0f * xp[1]);
}

// ---------------------------------------------------------------------------
// Prep B: E -> bf16 hi plane, mma-fragment order
// ---------------------------------------------------------------------------
__global__ void vq_prepB(const float* __restrict__ E) {
    int tid = blockIdx.x * blockDim.x + threadIdx.x;
    if (tid >= N_NB * 4 * 32 * 2) return;
    int reg = tid & 1, lane = (tid >> 1) & 31, kb = (tid >> 6) & 3, nb = tid >> 8;
    int g = lane >> 2, tg = lane & 3;
    int code = nb * 8 + g;
    int k = kb * 16 + tg * 2 + reg * 8;
    const float* ep = E + (size_t)code * D_DIM + k;
    g_Bh[tid] = pack_bf16(ep[0], ep[1]);
}

// ---------------------------------------------------------------------------
// Codebook norms
// ---------------------------------------------------------------------------
__global__ void vq_norm_kernel(const float* __restrict__ E) {
    int k = blockIdx.x * blockDim.x + threadIdx.x;
    if (k < K_CODES) {
        const float4* e = (const float4*)(E + (size_t)k * D_DIM);
        float s = 0.f;
#pragma unroll
        for (int i = 0; i < D_DIM / 4; ++i) {
            float4 v = e[i];
            s += v.x * v.x + v.y * v.y + v.z * v.z + v.w * v.w;
        }
        g_normE[k] = s;
    }
}

// ---------------------------------------------------------------------------
// Main: single-pass bf16 HMMA distance GEMM (wide margin) +
//       margin-candidate list + value-pruned exact fp32 refine
// ---------------------------------------------------------------------------
__global__ __launch_bounds__(THREADS) void vq_main_kernel(
    const float* __restrict__ X, const float* __restrict__ E,
    float* __restrict__ out)
{
    extern __shared__ char smem[];
    float* snorm = (float*)(smem + SM_NORM);
    float* candV = (float*)(smem + SM_CANDV);
    unsigned short* candI = (unsigned short*)(smem + SM_CANDI);
    int* cnt = (int*)(smem + SM_CNT);

    const int t = threadIdx.x;
    const int w = t >> 5, l = t & 31;
    const int g = l >> 2, tg = l & 3;
    const int rowBase = blockIdx.x * M_TILE;

    if (t < M_TILE) cnt[t] = 0;
    for (int i = t; i < K_CODES; i += THREADS) snorm[i] = g_normE[i];

    // A-hi fragments in registers for this warp's 16 rows
    const int mb = blockIdx.x * 8 + w;
    uint4 aH[4];
#pragma unroll
    for (int kb = 0; kb < 4; ++kb)
        aH[kb] = *(const uint4*)&g_Ah[((mb * 4 + kb) * 32 + l) * 4];

    float minv0 = 3.4e38f, minv1 = 3.4e38f;
    const int rL0 = w * 16 + g, rL1 = rL0 + 8;

#pragma unroll 1
    for (int tile = 0; tile < 4; ++tile) {
        __syncthreads();
        // stage B tile (32 nblocks, hi plane only) = 32KB
        {
            const uint4* src = (const uint4*)(g_Bh + tile * 8192);
            uint4* dst = (uint4*)(smem + SM_B);
#pragma unroll
            for (int i = 0; i < 8; ++i)
                dst[t + i * THREADS] = src[t + i * THREADS];
        }
        __syncthreads();

        const uint2* bq = (const uint2*)(smem + SM_B) + l;
#pragma unroll 1
        for (int nbl = 0; nbl < 32; ++nbl) {
            uint2 cbh[4];
#pragma unroll
            for (int kb = 0; kb < 4; ++kb) cbh[kb] = bq[kb * 32];
            bq += 128;

            const int c0 = tile * 256 + nbl * 8 + tg * 2;
            const float2 nn = *(const float2*)&snorm[c0];
            float acc[4] = {nn.x, nn.y, nn.x, nn.y};   // norm folded in
#pragma unroll
            for (int kb = 0; kb < 4; ++kb)
                mma_bf16(acc, (const uint32_t*)&aH[kb], cbh[kb].x, cbh[kb].y);
            const float d0 = acc[0], d1 = acc[1], d2 = acc[2], d3 = acc[3];
            // rare guard; store approx value + index for later pruning
            if (fminf(d0, d1) < minv0 + MARGIN || fminf(d2, d3) < minv1 + MARGIN) {
                if (d0 < minv0 + MARGIN) {
                    int p = atomicAdd(&cnt[rL0], 1);
                    if (p < CAP) { candV[rL0 * CAP + p] = d0; candI[rL0 * CAP + p] = (unsigned short)c0; }
                }
                minv0 = fminf(minv0, d0);
                if (d1 < minv0 + MARGIN) {
                    int p = atomicAdd(&cnt[rL0], 1);
                    if (p < CAP) { candV[rL0 * CAP + p] = d1; candI[rL0 * CAP + p] = (unsigned short)(c0 + 1); }
                }
                minv0 = fminf(minv0, d1);
                if (d2 < minv1 + MARGIN) {
                    int p = atomicAdd(&cnt[rL1], 1);
                    if (p < CAP) { candV[rL1 * CAP + p] = d2; candI[rL1 * CAP + p] = (unsigned short)c0; }
                }
                minv1 = fminf(minv1, d2);
                if (d3 < minv1 + MARGIN) {
                    int p = atomicAdd(&cnt[rL1], 1);
                    if (p < CAP) { candV[rL1 * CAP + p] = d3; candI[rL1 * CAP + p] = (unsigned short)(c0 + 1); }
                }
                minv1 = fminf(minv1, d3);
            } else {
                minv0 = fminf(minv0, fminf(d0, d1));
                minv1 = fminf(minv1, fminf(d2, d3));
            }
        }
    }
    __syncthreads();

    // ---- value-pruned exact refine + epilogue: one thread per row ----
    float* sLoss = (float*)(smem + SM_B);   // reuse B area
    if (t < M_TILE) {
        const int r = t;
        const float4* xr4 = (const float4*)(X + (size_t)(rowBase + r) * D_DIM);
        float bv = 3.4e38f;
        int bi = K_CODES;
        const int count = cnt[r];
        if (count > CAP) {
            // overflow fallback: exact scan over all codes (sized to never fire)
            for (int c = 0; c < K_CODES; ++c) {
                float dv = exact_dist(xr4, E, c, g_normE[c]);
                if (dv < bv) { bv = dv; bi = c; }
            }
        } else {
            float mA = 3.4e38f;
            for (int i = 0; i < count; ++i)
                mA = fminf(mA, candV[r * CAP + i]);
            // exact-recompute only candidates within MARGIN of best approx
            for (int i = 0; i < count; ++i) {
                if (candV[r * CAP + i] > mA + MARGIN) continue;
                int c = candI[r * CAP + i];
                float dv = exact_dist(xr4, E, c, g_normE[c]);
                if (dv < bv || (dv == bv && c < bi)) { bv = dv; bi = c; }
            }
        }
        const float4* erow = (const float4*)(E + (size_t)bi * D_DIM);
        float* qout = out + (size_t)(rowBase + r) * D_DIM;
        float lsum = 0.f;
#pragma unroll
        for (int i = 0; i < D_DIM / 4; ++i) {
            float4 q = erow[i], x = xr4[i];
            float e0 = q.x - x.x, e1 = q.y - x.y, e2 = q.z - x.z, e3 = q.w - x.w;
            lsum += e0 * e0 + e1 * e1 + e2 * e2 + e3 * e3;
            *(float4*)(qout + i * 4) = q;
        }
        out[OUT_IDX + rowBase + r] = (float)bi;
        sLoss[r] = lsum;
    }
    __syncthreads();
    if (t < 64) sLoss[t] += sLoss[t + 64];
    __syncthreads();
    if (t < 32) sLoss[t] += sLoss[t + 32];
    __syncthreads();
    if (t == 0) {
        float s = 0.f;
#pragma unroll
        for (int i = 0; i < 32; ++i) s += sLoss[i];
        g_partials[blockIdx.x] = s;
    }
}

// ---------------------------------------------------------------------------
// Final loss:  loss = 1.25 * mean((q - x)^2), deterministic tree
// ---------------------------------------------------------------------------
__global__ void vq_loss_kernel(float* __restrict__ out) {
    __shared__ float sh[NUM_BLOCKS];
    int t = threadIdx.x;
    sh[t] = g_partials[t];
    __syncthreads();
    for (int s = NUM_BLOCKS / 2; s > 0; s >>= 1) {
        if (t < s) sh[t] += sh[t + s];
        __syncthreads();
    }
    if (t == 0) out[OUT_LOSS] = sh[0] * (1.25f / (float)(N_ROWS * D_DIM));
}

// ---------------------------------------------------------------------------
extern "C" void kernel_launch(void* const* d_in, const int* in_sizes, int n_in,
                              void* d_out, int out_size) {
    const float* X = (const float*)d_in[0];
    const float* E = (const float*)d_in[1];
    float* out = (float*)d_out;

    cudaFuncSetAttribute(vq_main_kernel,
                         cudaFuncAttributeMaxDynamicSharedMemorySize, SM_TOTAL);

    vq_prepA<<<(N_MB * 4 * 32 * 4 + 255) / 256, 256>>>(X);
    vq_prepB<<<(N_NB * 4 * 32 * 2 + 255) / 256, 256>>>(E);
    vq_norm_kernel<<<(K_CODES + 255) / 256, 256>>>(E);
    vq_main_kernel<<<NUM_BLOCKS, THREADS, SM_TOTAL>>>(X, E, out);
    vq_loss_kernel<<<1, NUM_BLOCKS>>>(out);
}

// round 16
// speedup vs baseline: 1.3973x; 1.0841x over previous
#include <cuda_runtime.h>
#include <cuda_bf16.h>
#include <cstdint>

// ---------------- problem constants ----------------
#define N_ROWS   65536
#define K_CODES  1024
#define D_DIM    64
#define M_TILE   128                    // rows per CTA
#define THREADS  256
#define NUM_BLOCKS (N_ROWS / M_TILE)    // 512
#define N_MB     (N_ROWS / 16)          // 4096 A row-blocks
#define N_NB     (K_CODES / 8)          // 128 B code-blocks
#define CAP      80
#define MARGIN   1.0f

// Output layout (floats): [quantized 4194304][loss 1][indices 65536]
#define OUT_LOSS (N_ROWS * D_DIM)
#define OUT_IDX  (OUT_LOSS + 1)

// ---------------- device globals ----------------
__device__ uint32_t g_Ah[N_MB * 4 * 32 * 4];   // 8 MB
__device__ uint32_t g_Bh[N_NB * 4 * 32 * 2];   // 128 KB
__device__ float g_normE[K_CODES];
__device__ float g_partials[NUM_BLOCKS];

// ---------------- smem layout (bytes) ----------------
#define SM_B     0        // 32768: [nbl(32)][kb(4)][lane(32)] uint2
#define SM_NORM  32768    // 4096
#define SM_CANDV 36864    // 40960: 128 * CAP floats
#define SM_CANDI 77824    // 20480: 128 * CAP u16
#define SM_CNT   98304    // 512
#define SM_TOTAL 98816    // 96.5 KB -> 2 CTAs/SM

// ---------------- helpers ----------------
__device__ __forceinline__ uint32_t pack_bf16(float lo, float hi) {
    __nv_bfloat16 a = __float2bfloat16(lo);
    __nv_bfloat16 b = __float2bfloat16(hi);
    uint16_t ua = *(uint16_t*)&a, ub = *(uint16_t*)&b;
    return (uint32_t)ua | ((uint32_t)ub << 16);
}
__device__ __forceinline__ void mma_bf16(float* c, const uint32_t* a,
                                         uint32_t b0, uint32_t b1) {
    asm volatile(
        "mma.sync.aligned.m16n8k16.row.col.f32.bf16.bf16.f32 "
        "{%0,%1,%2,%3}, {%4,%5,%6,%7}, {%8,%9}, {%0,%1,%2,%3};"
        : "+f"(c[0]), "+f"(c[1]), "+f"(c[2]), "+f"(c[3])
        : "r"(a[0]), "r"(a[1]), "r"(a[2]), "r"(a[3]), "r"(b0), "r"(b1));
}
__device__ __forceinline__ float exact_dist(const float4* xr4, const float* E,
                                            int c, float ne) {
    const float4* er4 = (const float4*)(E + (size_t)c * D_DIM);
    float dot = 0.f;
#pragma unroll
    for (int i = 0; i < D_DIM / 4; ++i) {
        float4 x = xr4[i], e = er4[i];
        dot = fmaf(x.x, e.x, dot); dot = fmaf(x.y, e.y, dot);
        dot = fmaf(x.z, e.z, dot); dot = fmaf(x.w, e.w, dot);
    }
    return fmaf(-2.f, dot, ne);
}

// ---------------------------------------------------------------------------
// Prep A: (-2*X) -> bf16 hi plane, mma-fragment order
// ---------------------------------------------------------------------------
__global__ void vq_prepA(const float* __restrict__ X) {
    int tid = blockIdx.x * blockDim.x + threadIdx.x;
    if (tid >= N_MB * 4 * 32 * 4) return;
    int reg = tid & 3, lane = (tid >> 2) & 31, kb = (tid >> 7) & 3, mb = tid >> 9;
    int g = lane >> 2, tg = lane & 3;
    int row = mb * 16 + g + ((reg & 1) << 3);
    int col = kb * 16 + tg * 2 + ((reg & 2) << 2);
    const float* xp = X + (size_t)row * D_DIM + col;
    g_Ah[tid] = pack_bf16(-2.0f * xp[0], -2.0f * xp[1]);
}

// ---------------------------------------------------------------------------
// Prep B: E -> bf16 hi plane, mma-fragment order
// ---------------------------------------------------------------------------
__global__ void vq_prepB(const float* __restrict__ E) {
    int tid = blockIdx.x * blockDim.x + threadIdx.x;
    if (tid >= N_NB * 4 * 32 * 2) return;
    int reg = tid & 1, lane = (tid >> 1) & 31, kb = (tid >> 6) & 3, nb = tid >> 8;
    int g = lane >> 2, tg = lane & 3;
    int code = nb * 8 + g;
    int k = kb * 16 + tg * 2 + reg * 8;
    const float* ep = E + (size_t)code * D_DIM + k;
    g_Bh[tid] = pack_bf16(ep[0], ep[1]);
}

// ---------------------------------------------------------------------------
// Codebook norms
// ---------------------------------------------------------------------------
__global__ void vq_norm_kernel(const float* __restrict__ E) {
    int k = blockIdx.x * blockDim.x + threadIdx.x;
    if (k < K_CODES) {
        const float4* e = (const float4*)(E + (size_t)k * D_DIM);
        float s = 0.f;
#pragma unroll
        for (int i = 0; i < D_DIM / 4; ++i) {
            float4 v = e[i];
            s += v.x * v.x + v.y * v.y + v.z * v.z + v.w * v.w;
        }
        g_normE[k] = s;
    }
}

// per-code candidate push + running-min update (ascending order preserved)
#define PUSH_CODE(dv, code, minv, rL)                                          \
    do {                                                                       \
        if ((dv) < (minv) + MARGIN) {                                          \
            int p = atomicAdd(&cnt[rL], 1);                                    \
            if (p < CAP) { candV[(rL) * CAP + p] = (dv);                       \
                           candI[(rL) * CAP + p] = (unsigned short)(code); }   \
        }                                                                      \
        (minv) = fminf((minv), (dv));                                          \
    } while (0)

// ---------------------------------------------------------------------------
// Main: single-pass bf16 HMMA distance GEMM, TWO nblocks per iteration
//       (2 independent MMA chains) + margin-candidate list + exact refine
// ---------------------------------------------------------------------------
__global__ __launch_bounds__(THREADS) void vq_main_kernel(
    const float* __restrict__ X, const float* __restrict__ E,
    float* __restrict__ out)
{
    extern __shared__ char smem[];
    float* snorm = (float*)(smem + SM_NORM);
    float* candV = (float*)(smem + SM_CANDV);
    unsigned short* candI = (unsigned short*)(smem + SM_CANDI);
    int* cnt = (int*)(smem + SM_CNT);

    const int t = threadIdx.x;
    const int w = t >> 5, l = t & 31;
    const int g = l >> 2, tg = l & 3;
    const int rowBase = blockIdx.x * M_TILE;

    if (t < M_TILE) cnt[t] = 0;
    for (int i = t; i < K_CODES; i += THREADS) snorm[i] = g_normE[i];

    // A-hi fragments in registers for this warp's 16 rows
    const int mb = blockIdx.x * 8 + w;
    uint4 aH[4];
#pragma unroll
    for (int kb = 0; kb < 4; ++kb)
        aH[kb] = *(const uint4*)&g_Ah[((mb * 4 + kb) * 32 + l) * 4];

    float minv0 = 3.4e38f, minv1 = 3.4e38f;
    const int rL0 = w * 16 + g, rL1 = rL0 + 8;

#pragma unroll 1
    for (int tile = 0; tile < 4; ++tile) {
        __syncthreads();
        // stage B tile (32 nblocks, hi plane only) = 32KB
        {
            const uint4* src = (const uint4*)(g_Bh + tile * 8192);
            uint4* dst = (uint4*)(smem + SM_B);
#pragma unroll
            for (int i = 0; i < 8; ++i)
                dst[t + i * THREADS] = src[t + i * THREADS];
        }
        __syncthreads();

        const uint2* bq = (const uint2*)(smem + SM_B) + l;
#pragma unroll 1
        for (int nbl2 = 0; nbl2 < 16; ++nbl2) {
            // load B fragments for both nblocks of the pair
            uint2 ba[4], bb[4];
#pragma unroll
            for (int kb = 0; kb < 4; ++kb) {
                ba[kb] = bq[kb * 32];
                bb[kb] = bq[128 + kb * 32];
            }
            bq += 256;

            const int c0a = tile * 256 + nbl2 * 16 + tg * 2;   // first nblock
            const int c0b = c0a + 8;                            // second nblock
            const float2 nna = *(const float2*)&snorm[c0a];
            const float2 nnb = *(const float2*)&snorm[c0b];
            float accA[4] = {nna.x, nna.y, nna.x, nna.y};
            float accB[4] = {nnb.x, nnb.y, nnb.x, nnb.y};
            // two independent 4-deep MMA chains — scheduler interleaves
#pragma unroll
            for (int kb = 0; kb < 4; ++kb) {
                mma_bf16(accA, (const uint32_t*)&aH[kb], ba[kb].x, ba[kb].y);
                mma_bf16(accB, (const uint32_t*)&aH[kb], bb[kb].x, bb[kb].y);
            }

            // guards (ascending code order: all of nblock a, then nblock b)
            const float mAa = fminf(accA[0], accA[1]), mAb = fminf(accA[2], accA[3]);
            const float mBa = fminf(accB[0], accB[1]), mBb = fminf(accB[2], accB[3]);
            if (fminf(mAa, mBa) < minv0 + MARGIN || fminf(mAb, mBb) < minv1 + MARGIN) {
                PUSH_CODE(accA[0], c0a,     minv0, rL0);
                PUSH_CODE(accA[1], c0a + 1, minv0, rL0);
                PUSH_CODE(accA[2], c0a,     minv1, rL1);
                PUSH_CODE(accA[3], c0a + 1, minv1, rL1);
                PUSH_CODE(accB[0], c0b,     minv0, rL0);
                PUSH_CODE(accB[1], c0b + 1, minv0, rL0);
                PUSH_CODE(accB[2], c0b,     minv1, rL1);
                PUSH_CODE(accB[3], c0b + 1, minv1, rL1);
            } else {
                minv0 = fminf(minv0, fminf(mAa, mBa));
                minv1 = fminf(minv1, fminf(mAb, mBb));
            }
        }
    }
    __syncthreads();

    // ---- value-pruned exact refine + epilogue: one thread per row ----
    float* sLoss = (float*)(smem + SM_B);   // reuse B area
    if (t < M_TILE) {
        const int r = t;
        const float4* xr4 = (const float4*)(X + (size_t)(rowBase + r) * D_DIM);
        float bv = 3.4e38f;
        int bi = K_CODES;
        const int count = cnt[r];
        if (count > CAP) {
            // overflow fallback: exact scan over all codes (sized to never fire)
            for (int c = 0; c < K_CODES; ++c) {
                float dv = exact_dist(xr4, E, c, g_normE[c]);
                if (dv < bv) { bv = dv; bi = c; }
            }
        } else {
            float mA = 3.4e38f;
            for (int i = 0; i < count; ++i)
                mA = fminf(mA, candV[r * CAP + i]);
            for (int i = 0; i < count; ++i) {
                if (candV[r * CAP + i] > mA + MARGIN) continue;
                int c = candI[r * CAP + i];
                float dv = exact_dist(xr4, E, c, g_normE[c]);
                if (dv < bv || (dv == bv && c < bi)) { bv = dv; bi = c; }
            }
        }
        const float4* erow = (const float4*)(E + (size_t)bi * D_DIM);
        float* qout = out + (size_t)(rowBase + r) * D_DIM;
        float lsum = 0.f;
#pragma unroll
        for (int i = 0; i < D_DIM / 4; ++i) {
            float4 q = erow[i], x = xr4[i];
            float e0 = q.x - x.x, e1 = q.y - x.y, e2 = q.z - x.z, e3 = q.w - x.w;
            lsum += e0 * e0 + e1 * e1 + e2 * e2 + e3 * e3;
            *(float4*)(qout + i * 4) = q;
        }
        out[OUT_IDX + rowBase + r] = (float)bi;
        sLoss[r] = lsum;
    }
    __syncthreads();
    if (t < 64) sLoss[t] += sLoss[t + 64];
    __syncthreads();
    if (t < 32) sLoss[t] += sLoss[t + 32];
    __syncthreads();
    if (t == 0) {
        float s = 0.f;
#pragma unroll
        for (int i = 0; i < 32; ++i) s += sLoss[i];
        g_partials[blockIdx.x] = s;
    }
}

// ---------------------------------------------------------------------------
// Final loss:  loss = 1.25 * mean((q - x)^2), deterministic tree
// ---------------------------------------------------------------------------
__global__ void vq_loss_kernel(float* __restrict__ out) {
    __shared__ float sh[NUM_BLOCKS];
    int t = threadIdx.x;
    sh[t] = g_partials[t];
    __syncthreads();
    for (int s = NUM_BLOCKS / 2; s > 0; s >>= 1) {
        if (t < s) sh[t] += sh[t + s];
        __syncthreads();
    }
    if (t == 0) out[OUT_LOSS] = sh[0] * (1.25f / (float)(N_ROWS * D_DIM));
}

// ---------------------------------------------------------------------------
extern "C" void kernel_launch(void* const* d_in, const int* in_sizes, int n_in,
                              void* d_out, int out_size) {
    const float* X = (const float*)d_in[0];
    const float* E = (const float*)d_in[1];
    float* out = (float*)d_out;

    cudaFuncSetAttribute(vq_main_kernel,
                         cudaFuncAttributeMaxDynamicSharedMemorySize, SM_TOTAL);

    vq_prepA<<<(N_MB * 4 * 32 * 4 + 255) / 256, 256>>>(X);
    vq_prepB<<<(N_NB * 4 * 32 * 2 + 255) / 256, 256>>>(E);
    vq_norm_kernel<<<(K_CODES + 255) / 256, 256>>>(E);
    vq_main_kernel<<<NUM_BLOCKS, THREADS, SM_TOTAL>>>(X, E, out);
    vq_loss_kernel<<<1, NUM_BLOCKS>>>(out);
}

// round 17
// speedup vs baseline: 1.5074x; 1.0788x over previous
#include <cuda_runtime.h>
#include <cuda_bf16.h>
#include <cstdint>

// ---------------- problem constants ----------------
#define N_ROWS   65536
#define K_CODES  1024
#define D_DIM    64
#define M_TILE   128                    // rows per CTA
#define THREADS  256
#define NUM_BLOCKS (N_ROWS / M_TILE)    // 512
#define N_MB     (N_ROWS / 16)          // 4096 A row-blocks
#define N_NB     (K_CODES / 8)          // 128 B code-blocks
#define CAP      80
#define MARGIN   1.0f

// Output layout (floats): [quantized 4194304][loss 1][indices 65536]
#define OUT_LOSS (N_ROWS * D_DIM)
#define OUT_IDX  (OUT_LOSS + 1)

// ---------------- device globals ----------------
__device__ uint32_t g_Ah[N_MB * 4 * 32 * 4];   // 8 MB
__device__ uint32_t g_Bh[N_NB * 4 * 32 * 2];   // 128 KB
__device__ float g_normE[K_CODES];
__device__ float g_partials[NUM_BLOCKS];

// ---------------- smem layout (bytes) ----------------
#define SM_B     0        // 32768: [nbl(32)][kb(4)][lane(32)] uint2
#define SM_NORM  32768    // 4096
#define SM_CANDV 36864    // 40960: 128 * CAP floats
#define SM_CANDI 77824    // 20480: 128 * CAP u16
#define SM_CNT   98304    // 512
#define SM_TOTAL 98816    // 96.5 KB -> 2 CTAs/SM

// ---------------- helpers ----------------
__device__ __forceinline__ uint32_t pack_bf16(float lo, float hi) {
    __nv_bfloat16 a = __float2bfloat16(lo);
    __nv_bfloat16 b = __float2bfloat16(hi);
    uint16_t ua = *(uint16_t*)&a, ub = *(uint16_t*)&b;
    return (uint32_t)ua | ((uint32_t)ub << 16);
}
__device__ __forceinline__ void mma_bf16(float* c, const uint32_t* a,
                                         uint32_t b0, uint32_t b1) {
    asm volatile(
        "mma.sync.aligned.m16n8k16.row.col.f32.bf16.bf16.f32 "
        "{%0,%1,%2,%3}, {%4,%5,%6,%7}, {%8,%9}, {%0,%1,%2,%3};"
        : "+f"(c[0]), "+f"(c[1]), "+f"(c[2]), "+f"(c[3])
        : "r"(a[0]), "r"(a[1]), "r"(a[2]), "r"(a[3]), "r"(b0), "r"(b1));
}
__device__ __forceinline__ float exact_dist(const float4* xr4, const float* E,
                                            int c, float ne) {
    const float4* er4 = (const float4*)(E + (size_t)c * D_DIM);
    float dot = 0.f;
#pragma unroll
    for (int i = 0; i < D_DIM / 4; ++i) {
        float4 x = xr4[i], e = er4[i];
        dot = fmaf(x.x, e.x, dot); dot = fmaf(x.y, e.y, dot);
        dot = fmaf(x.z, e.z, dot); dot = fmaf(x.w, e.w, dot);
    }
    return fmaf(-2.f, dot, ne);
}

// ---------------------------------------------------------------------------
// Prep A: (-2*X) -> bf16 hi plane, mma-fragment order
// ---------------------------------------------------------------------------
__global__ void vq_prepA(const float* __restrict__ X) {
    int tid = blockIdx.x * blockDim.x + threadIdx.x;
    if (tid >= N_MB * 4 * 32 * 4) return;
    int reg = tid & 3, lane = (tid >> 2) & 31, kb = (tid >> 7) & 3, mb = tid >> 9;
    int g = lane >> 2, tg = lane & 3;
    int row = mb * 16 + g + ((reg & 1) << 3);
    int col = kb * 16 + tg * 2 + ((reg & 2) << 2);
    const float* xp = X + (size_t)row * D_DIM + col;
    g_Ah[tid] = pack_bf16(-2.0f * xp[0], -2.0f * xp[1]);
}

// ---------------------------------------------------------------------------
// Prep B: E -> bf16 hi plane, mma-fragment order
// ---------------------------------------------------------------------------
__global__ void vq_prepB(const float* __restrict__ E) {
    int tid = blockIdx.x * blockDim.x + threadIdx.x;
    if (tid >= N_NB * 4 * 32 * 2) return;
    int reg = tid & 1, lane = (tid >> 1) & 31, kb = (tid >> 6) & 3, nb = tid >> 8;
    int g = lane >> 2, tg = lane & 3;
    int code = nb * 8 + g;
    int k = kb * 16 + tg * 2 + reg * 8;
    const float* ep = E + (size_t)code * D_DIM + k;
    g_Bh[tid] = pack_bf16(ep[0], ep[1]);
}

// ---------------------------------------------------------------------------
// Codebook norms
// ---------------------------------------------------------------------------
__global__ void vq_norm_kernel(const float* __restrict__ E) {
    int k = blockIdx.x * blockDim.x + threadIdx.x;
    if (k < K_CODES) {
        const float4* e = (const float4*)(E + (size_t)k * D_DIM);
        float s = 0.f;
#pragma unroll
        for (int i = 0; i < D_DIM / 4; ++i) {
            float4 v = e[i];
            s += v.x * v.x + v.y * v.y + v.z * v.z + v.w * v.w;
        }
        g_normE[k] = s;
    }
}

// per-code candidate push + running-min update (ascending order preserved)
#define PUSH_CODE(dv, code, minv, rL)                                          \
    do {                                                                       \
        if ((dv) < (minv) + MARGIN) {                                          \
            int p = atomicAdd(&cnt[rL], 1);                                    \
            if (p < CAP) { candV[(rL) * CAP + p] = (dv);                       \
                           candI[(rL) * CAP + p] = (unsigned short)(code); }   \
        }                                                                      \
        (minv) = fminf((minv), (dv));                                          \
    } while (0)

// ---------------------------------------------------------------------------
// Main: single-pass bf16 HMMA distance GEMM, FOUR nblocks per iteration
//       (4 independent MMA chains) + margin-candidate list + exact refine
// ---------------------------------------------------------------------------
__global__ __launch_bounds__(THREADS) void vq_main_kernel(
    const float* __restrict__ X, const float* __restrict__ E,
    float* __restrict__ out)
{
    extern __shared__ char smem[];
    float* snorm = (float*)(smem + SM_NORM);
    float* candV = (float*)(smem + SM_CANDV);
    unsigned short* candI = (unsigned short*)(smem + SM_CANDI);
    int* cnt = (int*)(smem + SM_CNT);

    const int t = threadIdx.x;
    const int w = t >> 5, l = t & 31;
    const int g = l >> 2, tg = l & 3;
    const int rowBase = blockIdx.x * M_TILE;

    if (t < M_TILE) cnt[t] = 0;
    for (int i = t; i < K_CODES; i += THREADS) snorm[i] = g_normE[i];

    // A-hi fragments in registers for this warp's 16 rows
    const int mb = blockIdx.x * 8 + w;
    uint4 aH[4];
#pragma unroll
    for (int kb = 0; kb < 4; ++kb)
        aH[kb] = *(const uint4*)&g_Ah[((mb * 4 + kb) * 32 + l) * 4];

    float minv0 = 3.4e38f, minv1 = 3.4e38f;
    const int rL0 = w * 16 + g, rL1 = rL0 + 8;

#pragma unroll 1
    for (int tile = 0; tile < 4; ++tile) {
        __syncthreads();
        // stage B tile (32 nblocks, hi plane only) = 32KB
        {
            const uint4* src = (const uint4*)(g_Bh + tile * 8192);
            uint4* dst = (uint4*)(smem + SM_B);
#pragma unroll
            for (int i = 0; i < 8; ++i)
                dst[t + i * THREADS] = src[t + i * THREADS];
        }
        __syncthreads();

        const uint2* bq = (const uint2*)(smem + SM_B) + l;
#pragma unroll 1
        for (int nbl4 = 0; nbl4 < 8; ++nbl4) {
            // load B fragments for all four nblocks of the quad
            uint2 ba[4], bb[4], bc[4], bd[4];
#pragma unroll
            for (int kb = 0; kb < 4; ++kb) {
                ba[kb] = bq[kb * 32];
                bb[kb] = bq[128 + kb * 32];
                bc[kb] = bq[256 + kb * 32];
                bd[kb] = bq[384 + kb * 32];
            }
            bq += 512;

            const int c0a = tile * 256 + nbl4 * 32 + tg * 2;
            const int c0b = c0a + 8, c0c = c0a + 16, c0d = c0a + 24;
            const float2 nna = *(const float2*)&snorm[c0a];
            const float2 nnb = *(const float2*)&snorm[c0b];
            const float2 nnc = *(const float2*)&snorm[c0c];
            const float2 nnd = *(const float2*)&snorm[c0d];
            float accA[4] = {nna.x, nna.y, nna.x, nna.y};
            float accB[4] = {nnb.x, nnb.y, nnb.x, nnb.y};
            float accC[4] = {nnc.x, nnc.y, nnc.x, nnc.y};
            float accD[4] = {nnd.x, nnd.y, nnd.x, nnd.y};
            // four independent 4-deep MMA chains — scheduler interleaves
#pragma unroll
            for (int kb = 0; kb < 4; ++kb) {
                mma_bf16(accA, (const uint32_t*)&aH[kb], ba[kb].x, ba[kb].y);
                mma_bf16(accB, (const uint32_t*)&aH[kb], bb[kb].x, bb[kb].y);
                mma_bf16(accC, (const uint32_t*)&aH[kb], bc[kb].x, bc[kb].y);
                mma_bf16(accD, (const uint32_t*)&aH[kb], bd[kb].x, bd[kb].y);
            }

            // single guard over 32 codes; pushes in ascending code order
            const float m0 = fminf(fminf(fminf(accA[0], accA[1]), fminf(accB[0], accB[1])),
                                   fminf(fminf(accC[0], accC[1]), fminf(accD[0], accD[1])));
            const float m1 = fminf(fminf(fminf(accA[2], accA[3]), fminf(accB[2], accB[3])),
                                   fminf(fminf(accC[2], accC[3]), fminf(accD[2], accD[3])));
            if (m0 < minv0 + MARGIN || m1 < minv1 + MARGIN) {
                PUSH_CODE(accA[0], c0a,     minv0, rL0);
                PUSH_CODE(accA[1], c0a + 1, minv0, rL0);
                PUSH_CODE(accA[2], c0a,     minv1, rL1);
                PUSH_CODE(accA[3], c0a + 1, minv1, rL1);
                PUSH_CODE(accB[0], c0b,     minv0, rL0);
                PUSH_CODE(accB[1], c0b + 1, minv0, rL0);
                PUSH_CODE(accB[2], c0b,     minv1, rL1);
                PUSH_CODE(accB[3], c0b + 1, minv1, rL1);
                PUSH_CODE(accC[0], c0c,     minv0, rL0);
                PUSH_CODE(accC[1], c0c + 1, minv0, rL0);
                PUSH_CODE(accC[2], c0c,     minv1, rL1);
                PUSH_CODE(accC[3], c0c + 1, minv1, rL1);
                PUSH_CODE(accD[0], c0d,     minv0, rL0);
                PUSH_CODE(accD[1], c0d + 1, minv0, rL0);
                PUSH_CODE(accD[2], c0d,     minv1, rL1);
                PUSH_CODE(accD[3], c0d + 1, minv1, rL1);
            } else {
                minv0 = fminf(minv0, m0);
                minv1 = fminf(minv1, m1);
            }
        }
    }
    __syncthreads();

    // ---- value-pruned exact refine + epilogue: one thread per row ----
    float* sLoss = (float*)(smem + SM_B);   // reuse B area
    if (t < M_TILE) {
        const int r = t;
        const float4* xr4 = (const float4*)(X + (size_t)(rowBase + r) * D_DIM);
        float bv = 3.4e38f;
        int bi = K_CODES;
        const int count = cnt[r];
        if (count > CAP) {
            // overflow fallback: exact scan over all codes (sized to never fire)
            for (int c = 0; c < K_CODES; ++c) {
                float dv = exact_dist(xr4, E, c, g_normE[c]);
                if (dv < bv) { bv = dv; bi = c; }
            }
        } else {
            float mA = 3.4e38f;
            for (int i = 0; i < count; ++i)
                mA = fminf(mA, candV[r * CAP + i]);
            for (int i = 0; i < count; ++i) {
                if (candV[r * CAP + i] > mA + MARGIN) continue;
                int c = candI[r * CAP + i];
                float dv = exact_dist(xr4, E, c, g_normE[c]);
                if (dv < bv || (dv == bv && c < bi)) { bv = dv; bi = c; }
            }
        }
        const float4* erow = (const float4*)(E + (size_t)bi * D_DIM);
        float* qout = out + (size_t)(rowBase + r) * D_DIM;
        float lsum = 0.f;
#pragma unroll
        for (int i = 0; i < D_DIM / 4; ++i) {
            float4 q = erow[i], x = xr4[i];
            float e0 = q.x - x.x, e1 = q.y - x.y, e2 = q.z - x.z, e3 = q.w - x.w;
            lsum += e0 * e0 + e1 * e1 + e2 * e2 + e3 * e3;
            *(float4*)(qout + i * 4) = q;
        }
        out[OUT_IDX + rowBase + r] = (float)bi;
        sLoss[r] = lsum;
    }
    __syncthreads();
    if (t < 64) sLoss[t] += sLoss[t + 64];
    __syncthreads();
    if (t < 32) sLoss[t] += sLoss[t + 32];
    __syncthreads();
    if (t == 0) {
        float s = 0.f;
#pragma unroll
        for (int i = 0; i < 32; ++i) s += sLoss[i];
        g_partials[blockIdx.x] = s;
    }
}

// ---------------------------------------------------------------------------
// Final loss:  loss = 1.25 * mean((q - x)^2), deterministic tree
// ---------------------------------------------------------------------------
__global__ void vq_loss_kernel(float* __restrict__ out) {
    __shared__ float sh[NUM_BLOCKS];
    int t = threadIdx.x;
    sh[t] = g_partials[t];
    __syncthreads();
    for (int s = NUM_BLOCKS / 2; s > 0; s >>= 1) {
        if (t < s) sh[t] += sh[t + s];
        __syncthreads();
    }
    if (t == 0) out[OUT_LOSS] = sh[0] * (1.25f / (float)(N_ROWS * D_DIM));
}

// ---------------------------------------------------------------------------
extern "C" void kernel_launch(void* const* d_in, const int* in_sizes, int n_in,
                              void* d_out, int out_size) {
    const float* X = (const float*)d_in[0];
    const float* E = (const float*)d_in[1];
    float* out = (float*)d_out;

    cudaFuncSetAttribute(vq_main_kernel,
                         cudaFuncAttributeMaxDynamicSharedMemorySize, SM_TOTAL);

    vq_prepA<<<(N_MB * 4 * 32 * 4 + 255) / 256, 256>>>(X);
    vq_prepB<<<(N_NB * 4 * 32 * 2 + 255) / 256, 256>>>(E);
    vq_norm_kernel<<<(K_CODES + 255) / 256, 256>>>(E);
    vq_main_kernel<<<NUM_BLOCKS, THREADS, SM_TOTAL>>>(X, E, out);
    vq_loss_kernel<<<1, NUM_BLOCKS>>>(out);
}